// round 6
// baseline (speedup 1.0000x reference)
#include <cuda_runtime.h>
#include <cuda_bf16.h>
#include <math.h>

// ============================================================================
// EnhancedValueNetwork — unique-input table (14^4 = 38416 rows), fused stats.
// GEMMs: packed-f32x2 (FFMA2), warp-per-column-slice layout:
//   - W pre-duplicated in smem, read via broadcast (conflict-free)
//   - z as natural row-pairs, strided lane assignment (conflict-free LDS.64)
//   - zero packing MOVs in the inner loop
// R6 fix: __syncthreads() BEFORE prefetch(0) — a_sh/c_sh race in R5.
// ============================================================================

#define UNQ 38416
#define BMAX 524288

__device__ float  g_h1[UNQ * 128];
__device__ float  g_h2[UNQ * 128];
__device__ float  g_h3[UNQ * 64];
__device__ float  g_out_tab[UNQ];
__device__ unsigned short g_idx[BMAX];
__device__ int    g_hist[UNQ];
__device__ double g_sums1[256];
__device__ double g_sums2[256];
__device__ double g_sums3[128];

// ---- packed f32x2 helpers --------------------------------------------------
__device__ __forceinline__ void fma2(unsigned long long& d, unsigned long long a,
                                     unsigned long long b) {
    asm("fma.rn.f32x2 %0, %1, %2, %0;" : "+l"(d) : "l"(a), "l"(b));
}
__device__ __forceinline__ void unpk(unsigned long long v, float& lo, float& hi) {
    unsigned int l, h;
    asm("mov.b64 {%0, %1}, %2;" : "=r"(l), "=r"(h) : "l"(v));
    lo = __uint_as_float(l); hi = __uint_as_float(h);
}

// ---------------------------------------------------------------------------
__global__ void zero_kernel() {
    int i = blockIdx.x * blockDim.x + threadIdx.x;
    int stride = gridDim.x * blockDim.x;
    for (int t = i; t < UNQ; t += stride) g_hist[t] = 0;
    if (i < 256) { g_sums1[i] = 0.0; g_sums2[i] = 0.0; }
    if (i < 128) { g_sums3[i] = 0.0; }
}

// ---------------------------------------------------------------------------
__global__ void hist_kernel(const float* __restrict__ x, int B) {
    int i = blockIdx.x * blockDim.x + threadIdx.x;
    if (i >= B) return;
    float4 v = __ldg(reinterpret_cast<const float4*>(x) + (size_t)i * 4);
    int u = (int)v.x + 14 * (int)v.y + 196 * (int)v.z + 2744 * (int)v.w;
    g_idx[i] = (unsigned short)u;
    atomicAdd(&g_hist[u], 1);
}

// ---------------------------------------------------------------------------
__device__ __forceinline__ float score24(float v) {
    float t = fabsf(v - 24.0f) / 24.0f;
    return 1.0f - fminf(t, 1.0f);
}

// Layer 1: features + h1 = z0 @ W1 + b1, fused weighted column stats.
__global__ void __launch_bounds__(128) l1_kernel(const float* __restrict__ w1,
                                                 const float* __restrict__ b1) {
    __shared__ __align__(16) float zsh[128][20];
    __shared__ float cnt_sh[128];
    int tid  = threadIdx.x;
    int base = blockIdx.x * 128;
    int row  = base + tid;

    #pragma unroll
    for (int k = 0; k < 20; k++) zsh[tid][k] = 0.0f;
    cnt_sh[tid] = (row < UNQ) ? (float)__ldg(&g_hist[row]) : 0.0f;

    if (row < UNQ) {
        int u = row;
        int n0 = u % 14; u /= 14;
        int n1 = u % 14; u /= 14;
        int n2 = u % 14;
        int n3 = u / 14;
        float v0 = (float)n0, v1 = (float)n1, v2 = (float)n2, v3 = (float)n3;
        zsh[tid][0] = v0; zsh[tid][1] = v1; zsh[tid][2] = v2; zsh[tid][3] = v3;

        float s0 = 0.f, s1 = 0.f, s2 = 0.f, s3 = 0.f; int m = 0;
        if (v0 != 0.f) { s0 = v0; m = 1; }
        if (v1 != 0.f) { if (m == 0) s0 = v1; else s1 = v1; m++; }
        if (v2 != 0.f) { if (m == 0) s0 = v2; else if (m == 1) s1 = v2; else s2 = v2; m++; }
        if (v3 != 0.f) { if (m == 0) s0 = v3; else if (m == 1) s1 = v3; else if (m == 2) s2 = v3; else s3 = v3; m++; }

        int rank = 0;
        auto emit = [&](float A, float Bv, int q) {
            if (q < m) {
                if (rank < 3) {
                    float* fp = &zsh[tid][4 + rank * 4];
                    fp[0] = score24(A + Bv);
                    fp[1] = score24(A * Bv);
                    fp[2] = score24(A - Bv);
                    fp[3] = score24(A / Bv);
                }
                rank++;
            }
        };
        emit(s0, s1, 1); emit(s0, s2, 2); emit(s0, s3, 3);
        emit(s1, s2, 2); emit(s1, s3, 3); emit(s2, s3, 3);
    }

    // packed weight pairs over k: wp[q] = (w1[2q][tid], w1[2q+1][tid])
    unsigned long long wp[8];
    #pragma unroll
    for (int q = 0; q < 8; q++) {
        float wl = __ldg(&w1[(2 * q) * 128 + tid]);
        float wh = __ldg(&w1[(2 * q + 1) * 128 + tid]);
        unsigned long long r;
        asm("mov.b64 %0, {%1, %2};" : "=l"(r)
            : "r"(__float_as_uint(wl)), "r"(__float_as_uint(wh)));
        wp[q] = r;
    }
    float bb = __ldg(&b1[tid]);

    __syncthreads();

    float s = 0.f, ss = 0.f;
    int nrows = min(128, UNQ - base);
    for (int r = 0; r < nrows; r++) {
        const unsigned long long* zp =
            reinterpret_cast<const unsigned long long*>(&zsh[r][0]);
        unsigned long long accp = 0ull;
        #pragma unroll
        for (int q = 0; q < 8; q++) fma2(accp, zp[q], wp[q]);
        float lo, hi; unpk(accp, lo, hi);
        float acc = bb + lo + hi;
        g_h1[(size_t)(base + r) * 128 + tid] = acc;
        float ch = cnt_sh[r] * acc;
        s += ch;
        ss = fmaf(ch, acc, ss);
    }
    atomicAdd(&g_sums1[tid], (double)s);
    atomicAdd(&g_sums1[128 + tid], (double)ss);
}

// ---------------------------------------------------------------------------
// FFMA2 SGEMM over the table: out = relu(a*in + c) @ W + bias.
// LAYER 0: 128 rows x 128 cols (h1->h2, W=w2).
// LAYER 1: 256 rows x  64 cols (h2->h3, W=w3).
// 256 threads = 8 warps. Warp w owns cols [w*CPW, (w+1)*CPW), ALL rows.
// Lane owns row-pairs {lane + 32*j}. Accumulators: PPL row-pairs x CPW cols.
template <int LAYER>
__global__ void __launch_bounds__(256, 2) gemm_kernel(const float* __restrict__ W,
                                                      const float* __restrict__ bias,
                                                      const float* __restrict__ gam,
                                                      const float* __restrict__ bet,
                                                      double invB) {
    constexpr int NOUT = (LAYER == 0) ? 128 : 64;
    constexpr int ROWS = (LAYER == 0) ? 128 : 256;
    constexpr int CPW  = NOUT / 8;        // cols per warp: 16 / 8
    constexpr int PPL  = ROWS / 64;       // row-pairs per lane: 2 / 4
    constexpr int TPR  = 256 / ROWS;      // staging threads per row: 2 / 1
    constexpr int QPT  = 4 / TPR;         // k-quads staged per thread: 2 / 4
    constexpr int NWQ  = NOUT / 64;       // W float4 loads per thread: 2 / 1

    const float*  in_tab   = (LAYER == 0) ? g_h1 : g_h2;
    float*        out_tab  = (LAYER == 0) ? g_h2 : g_h3;
    const double* sums_in  = (LAYER == 0) ? g_sums1 : g_sums2;
    double*       sums_out = (LAYER == 0) ? g_sums2 : g_sums3;

    __shared__ __align__(16) float zt[16][ROWS];        // k-major z
    __shared__ __align__(16) float wt2[16][2 * NOUT];   // k-major W, dup'd
    __shared__ float a_sh[128], c_sh[128];
    __shared__ float cnt_sh[ROWS];
    __shared__ float psum[NOUT], psum2[NOUT];

    int tid   = threadIdx.x;
    int base  = blockIdx.x * ROWS;
    int nrows = min(ROWS, UNQ - base);

    if (tid < 128) {
        double mu  = sums_in[tid] * invB;
        double var = sums_in[128 + tid] * invB - mu * mu;
        float aj = __ldg(&gam[tid]) * rsqrtf((float)var + 1e-5f);
        a_sh[tid] = aj;
        c_sh[tid] = __ldg(&bet[tid]) - aj * (float)mu;
    }
    #pragma unroll
    for (int r = tid; r < ROWS; r += 256)
        cnt_sh[r] = (base + r < UNQ) ? (float)__ldg(&g_hist[base + r]) : 0.0f;
    if (tid < NOUT) { psum[tid] = 0.0f; psum2[tid] = 0.0f; }

    __syncthreads();   // *** R6 FIX: a_sh/c_sh must be visible before prefetch(0) ***

    // staging roles
    const int zrow = tid % ROWS;
    const int zq0  = tid / ROWS;
    const bool zvalid = (zrow < nrows);
    const float* zsrc = in_tab + (size_t)(base + zrow) * 128;

    // compute roles
    const int warp = tid >> 5;
    const int lane = tid & 31;

    float4 pz[QPT];
    float4 pw[NWQ];

    auto prefetch = [&](int c) {
        #pragma unroll
        for (int j = 0; j < QPT; j++) {
            int kg = c * 16 + (zq0 + j * TPR) * 4;
            float4 v = zvalid ? __ldg(reinterpret_cast<const float4*>(zsrc + kg))
                              : make_float4(0.f, 0.f, 0.f, 0.f);
            v.x = fmaxf(fmaf(a_sh[kg + 0], v.x, c_sh[kg + 0]), 0.0f);
            v.y = fmaxf(fmaf(a_sh[kg + 1], v.y, c_sh[kg + 1]), 0.0f);
            v.z = fmaxf(fmaf(a_sh[kg + 2], v.z, c_sh[kg + 2]), 0.0f);
            v.w = fmaxf(fmaf(a_sh[kg + 3], v.w, c_sh[kg + 3]), 0.0f);
            if (!zvalid) v = make_float4(0.f, 0.f, 0.f, 0.f);
            pz[j] = v;
        }
        #pragma unroll
        for (int q = 0; q < NWQ; q++) {
            int f  = tid + q * 256;
            int k  = f / (NOUT / 4);
            int c4 = f % (NOUT / 4);
            pw[q] = __ldg(reinterpret_cast<const float4*>(W + (size_t)(c * 16 + k) * NOUT) + c4);
        }
    };

    auto store_stage = [&]() {
        #pragma unroll
        for (int j = 0; j < QPT; j++) {
            int kk = (zq0 + j * TPR) * 4;
            zt[kk + 0][zrow] = pz[j].x;
            zt[kk + 1][zrow] = pz[j].y;
            zt[kk + 2][zrow] = pz[j].z;
            zt[kk + 3][zrow] = pz[j].w;
        }
        #pragma unroll
        for (int q = 0; q < NWQ; q++) {
            int f  = tid + q * 256;
            int k  = f / (NOUT / 4);
            int c4 = f % (NOUT / 4);
            float2* d = reinterpret_cast<float2*>(&wt2[k][8 * c4]);
            d[0] = make_float2(pw[q].x, pw[q].x);
            d[1] = make_float2(pw[q].y, pw[q].y);
            d[2] = make_float2(pw[q].z, pw[q].z);
            d[3] = make_float2(pw[q].w, pw[q].w);
        }
    };

    unsigned long long acc[PPL][CPW];
    #pragma unroll
    for (int j = 0; j < PPL; j++)
        #pragma unroll
        for (int cc = 0; cc < CPW; cc++) acc[j][cc] = 0ull;

    prefetch(0);
    store_stage();
    __syncthreads();

    for (int c = 0; c < 8; c++) {
        if (c < 7) prefetch(c + 1);

        #pragma unroll
        for (int k = 0; k < 16; k++) {
            unsigned long long zp[PPL];
            #pragma unroll
            for (int j = 0; j < PPL; j++)
                zp[j] = *reinterpret_cast<const unsigned long long*>(
                            &zt[k][2 * (lane + 32 * j)]);

            unsigned long long wp[CPW];
            const ulonglong2* wb =
                reinterpret_cast<const ulonglong2*>(&wt2[k][warp * 2 * CPW]);
            #pragma unroll
            for (int i = 0; i < CPW / 2; i++) {
                ulonglong2 t = wb[i];
                wp[2 * i] = t.x; wp[2 * i + 1] = t.y;
            }

            #pragma unroll
            for (int j = 0; j < PPL; j++)
                #pragma unroll
                for (int cc = 0; cc < CPW; cc++)
                    fma2(acc[j][cc], zp[j], wp[cc]);
        }

        __syncthreads();
        if (c < 7) {
            store_stage();
            __syncthreads();
        }
    }

    // epilogue: bias, store, fused weighted stats
    float bv[CPW];
    #pragma unroll
    for (int cc = 0; cc < CPW; cc++) bv[cc] = __ldg(&bias[warp * CPW + cc]);

    float s[CPW], ssq[CPW];
    #pragma unroll
    for (int cc = 0; cc < CPW; cc++) { s[cc] = 0.0f; ssq[cc] = 0.0f; }

    #pragma unroll
    for (int j = 0; j < PPL; j++) {
        int rp = lane + 32 * j;
        int r0 = 2 * rp, r1 = 2 * rp + 1;
        float c0 = cnt_sh[r0], c1 = cnt_sh[r1];
        float vlo[CPW], vhi[CPW];
        #pragma unroll
        for (int cc = 0; cc < CPW; cc++) {
            float lo, hi; unpk(acc[j][cc], lo, hi);
            vlo[cc] = lo + bv[cc];
            vhi[cc] = hi + bv[cc];
            float cv0 = c0 * vlo[cc];
            float cv1 = c1 * vhi[cc];
            s[cc] += cv0 + cv1;
            ssq[cc] = fmaf(cv0, vlo[cc], ssq[cc]);
            ssq[cc] = fmaf(cv1, vhi[cc], ssq[cc]);
        }
        if (r0 < nrows) {
            float* op = out_tab + (size_t)(base + r0) * NOUT + warp * CPW;
            #pragma unroll
            for (int q4 = 0; q4 < CPW / 4; q4++)
                reinterpret_cast<float4*>(op)[q4] =
                    make_float4(vlo[4*q4], vlo[4*q4+1], vlo[4*q4+2], vlo[4*q4+3]);
        }
        if (r1 < nrows) {
            float* op = out_tab + (size_t)(base + r1) * NOUT + warp * CPW;
            #pragma unroll
            for (int q4 = 0; q4 < CPW / 4; q4++)
                reinterpret_cast<float4*>(op)[q4] =
                    make_float4(vhi[4*q4], vhi[4*q4+1], vhi[4*q4+2], vhi[4*q4+3]);
        }
    }

    // reduce lanes 16..31 into 0..15, then shared atomics (16-way max)
    #pragma unroll
    for (int cc = 0; cc < CPW; cc++) {
        s[cc]   += __shfl_xor_sync(0xFFFFFFFFu, s[cc], 16);
        ssq[cc] += __shfl_xor_sync(0xFFFFFFFFu, ssq[cc], 16);
    }
    if (lane < 16) {
        #pragma unroll
        for (int cc = 0; cc < CPW; cc++) {
            atomicAdd(&psum[warp * CPW + cc], s[cc]);
            atomicAdd(&psum2[warp * CPW + cc], ssq[cc]);
        }
    }
    __syncthreads();
    if (tid < NOUT) {
        atomicAdd(&sums_out[tid], (double)psum[tid]);
        atomicAdd(&sums_out[NOUT + tid], (double)psum2[tid]);
    }
}

// ---------------------------------------------------------------------------
__global__ void __launch_bounds__(256) l4_kernel(const float* __restrict__ w4,
                                                 const float* __restrict__ b4,
                                                 const float* __restrict__ g3,
                                                 const float* __restrict__ be3,
                                                 double invB) {
    __shared__ float a_sh[64], c_sh[64];
    int tid = threadIdx.x;
    if (tid < 64) {
        double mu  = g_sums3[tid] * invB;
        double var = g_sums3[64 + tid] * invB - mu * mu;
        float aj = __ldg(&g3[tid]) * rsqrtf((float)var + 1e-5f);
        a_sh[tid] = aj;
        c_sh[tid] = __ldg(&be3[tid]) - aj * (float)mu;
    }
    __syncthreads();

    int u = blockIdx.x * blockDim.x + tid;
    if (u >= UNQ) return;
    const float4* hr = reinterpret_cast<const float4*>(g_h3 + (size_t)u * 64);
    float acc = __ldg(b4);
    #pragma unroll
    for (int q = 0; q < 16; q++) {
        float4 h = hr[q];
        int k = q * 4;
        float z0 = fmaxf(fmaf(a_sh[k + 0], h.x, c_sh[k + 0]), 0.0f);
        float z1 = fmaxf(fmaf(a_sh[k + 1], h.y, c_sh[k + 1]), 0.0f);
        float z2 = fmaxf(fmaf(a_sh[k + 2], h.z, c_sh[k + 2]), 0.0f);
        float z3 = fmaxf(fmaf(a_sh[k + 3], h.w, c_sh[k + 3]), 0.0f);
        acc = fmaf(z0, __ldg(&w4[k + 0]), acc);
        acc = fmaf(z1, __ldg(&w4[k + 1]), acc);
        acc = fmaf(z2, __ldg(&w4[k + 2]), acc);
        acc = fmaf(z3, __ldg(&w4[k + 3]), acc);
    }
    g_out_tab[u] = 1.0f / (1.0f + expf(-acc));
}

// ---------------------------------------------------------------------------
__global__ void gather_kernel(float* __restrict__ out, int B) {
    int i = blockIdx.x * blockDim.x + threadIdx.x;
    if (i >= B) return;
    out[i] = g_out_tab[g_idx[i]];
}

// ============================================================================
extern "C" void kernel_launch(void* const* d_in, const int* in_sizes, int n_in,
                              void* d_out, int out_size) {
    const float* x   = (const float*)d_in[0];
    const float* w1  = (const float*)d_in[1];
    const float* b1  = (const float*)d_in[2];
    const float* g1  = (const float*)d_in[3];
    const float* be1 = (const float*)d_in[4];
    const float* w2  = (const float*)d_in[5];
    const float* b2  = (const float*)d_in[6];
    const float* g2  = (const float*)d_in[7];
    const float* be2 = (const float*)d_in[8];
    const float* w3  = (const float*)d_in[9];
    const float* b3  = (const float*)d_in[10];
    const float* g3  = (const float*)d_in[11];
    const float* be3 = (const float*)d_in[12];
    const float* w4  = (const float*)d_in[13];
    const float* b4  = (const float*)d_in[14];
    float* out = (float*)d_out;

    int B = in_sizes[0] / 16;
    double invB = 1.0 / (double)B;

    zero_kernel<<<64, 256>>>();
    hist_kernel<<<(B + 255) / 256, 256>>>(x, B);
    l1_kernel<<<(UNQ + 127) / 128, 128>>>(w1, b1);
    gemm_kernel<0><<<(UNQ + 127) / 128, 256>>>(w2, b2, g1, be1, invB);
    gemm_kernel<1><<<(UNQ + 255) / 256, 256>>>(w3, b3, g2, be2, invB);
    l4_kernel<<<(UNQ + 255) / 256, 256>>>(w4, b4, g3, be3, invB);
    gather_kernel<<<(B + 255) / 256, 256>>>(out, B);
}

// round 7
// speedup vs baseline: 1.4345x; 1.4345x over previous
#include <cuda_runtime.h>
#include <cuda_bf16.h>
#include <math.h>

// ============================================================================
// EnhancedValueNetwork — unique-input table (14^4 = 38416 rows), fused stats.
// GEMMs: FFMA2 with COLUMN-pair packing (W pairs natural from LDS.128, only
// 8 z-dup MOVs/k), 48B-strided W smem (conflict-free), 1 barrier per chunk.
// ============================================================================

#define UNQ 38416
#define BMAX 524288

__device__ float  g_h1[UNQ * 128];
__device__ float  g_h2[UNQ * 128];
__device__ float  g_h3[UNQ * 64];
__device__ float  g_out_tab[UNQ];
__device__ unsigned short g_idx[BMAX];
__device__ int    g_hist[UNQ];
__device__ double g_sums1[256];
__device__ double g_sums2[256];
__device__ double g_sums3[128];

// ---- packed f32x2 helpers --------------------------------------------------
__device__ __forceinline__ void fma2(unsigned long long& d, unsigned long long a,
                                     unsigned long long b) {
    asm("fma.rn.f32x2 %0, %1, %2, %0;" : "+l"(d) : "l"(a), "l"(b));
}
__device__ __forceinline__ unsigned long long dup2(float v) {
    unsigned long long r;
    asm("mov.b64 %0, {%1, %1};" : "=l"(r) : "r"(__float_as_uint(v)));
    return r;
}
__device__ __forceinline__ void unpk(unsigned long long v, float& lo, float& hi) {
    unsigned int l, h;
    asm("mov.b64 {%0, %1}, %2;" : "=r"(l), "=r"(h) : "l"(v));
    lo = __uint_as_float(l); hi = __uint_as_float(h);
}

// ---------------------------------------------------------------------------
__global__ void zero_kernel() {
    int i = blockIdx.x * blockDim.x + threadIdx.x;
    int stride = gridDim.x * blockDim.x;
    for (int t = i; t < UNQ; t += stride) g_hist[t] = 0;
    if (i < 256) { g_sums1[i] = 0.0; g_sums2[i] = 0.0; }
    if (i < 128) { g_sums3[i] = 0.0; }
}

// ---------------------------------------------------------------------------
__global__ void hist_kernel(const float* __restrict__ x, int B) {
    int i = blockIdx.x * blockDim.x + threadIdx.x;
    if (i >= B) return;
    float4 v = __ldg(reinterpret_cast<const float4*>(x) + (size_t)i * 4);
    int u = (int)v.x + 14 * (int)v.y + 196 * (int)v.z + 2744 * (int)v.w;
    g_idx[i] = (unsigned short)u;
    atomicAdd(&g_hist[u], 1);
}

// ---------------------------------------------------------------------------
__device__ __forceinline__ float score24(float v) {
    float t = fabsf(v - 24.0f) / 24.0f;
    return 1.0f - fminf(t, 1.0f);
}

// Layer 1: features + h1 = z0 @ W1 + b1, fused weighted column stats.
__global__ void __launch_bounds__(128) l1_kernel(const float* __restrict__ w1,
                                                 const float* __restrict__ b1) {
    __shared__ __align__(16) float zsh[128][20];
    __shared__ float cnt_sh[128];
    int tid  = threadIdx.x;
    int base = blockIdx.x * 128;
    int row  = base + tid;

    #pragma unroll
    for (int k = 0; k < 20; k++) zsh[tid][k] = 0.0f;
    cnt_sh[tid] = (row < UNQ) ? (float)__ldg(&g_hist[row]) : 0.0f;

    if (row < UNQ) {
        int u = row;
        int n0 = u % 14; u /= 14;
        int n1 = u % 14; u /= 14;
        int n2 = u % 14;
        int n3 = u / 14;
        float v0 = (float)n0, v1 = (float)n1, v2 = (float)n2, v3 = (float)n3;
        zsh[tid][0] = v0; zsh[tid][1] = v1; zsh[tid][2] = v2; zsh[tid][3] = v3;

        float s0 = 0.f, s1 = 0.f, s2 = 0.f, s3 = 0.f; int m = 0;
        if (v0 != 0.f) { s0 = v0; m = 1; }
        if (v1 != 0.f) { if (m == 0) s0 = v1; else s1 = v1; m++; }
        if (v2 != 0.f) { if (m == 0) s0 = v2; else if (m == 1) s1 = v2; else s2 = v2; m++; }
        if (v3 != 0.f) { if (m == 0) s0 = v3; else if (m == 1) s1 = v3; else if (m == 2) s2 = v3; else s3 = v3; m++; }

        int rank = 0;
        auto emit = [&](float A, float Bv, int q) {
            if (q < m) {
                if (rank < 3) {
                    float* fp = &zsh[tid][4 + rank * 4];
                    fp[0] = score24(A + Bv);
                    fp[1] = score24(A * Bv);
                    fp[2] = score24(A - Bv);
                    fp[3] = score24(A / Bv);
                }
                rank++;
            }
        };
        emit(s0, s1, 1); emit(s0, s2, 2); emit(s0, s3, 3);
        emit(s1, s2, 2); emit(s1, s3, 3); emit(s2, s3, 3);
    }

    unsigned long long wp[8];
    #pragma unroll
    for (int q = 0; q < 8; q++) {
        float wl = __ldg(&w1[(2 * q) * 128 + tid]);
        float wh = __ldg(&w1[(2 * q + 1) * 128 + tid]);
        unsigned long long r;
        asm("mov.b64 %0, {%1, %2};" : "=l"(r)
            : "r"(__float_as_uint(wl)), "r"(__float_as_uint(wh)));
        wp[q] = r;
    }
    float bb = __ldg(&b1[tid]);

    __syncthreads();

    float s = 0.f, ss = 0.f;
    int nrows = min(128, UNQ - base);
    for (int r = 0; r < nrows; r++) {
        const unsigned long long* zp =
            reinterpret_cast<const unsigned long long*>(&zsh[r][0]);
        unsigned long long accp = 0ull;
        #pragma unroll
        for (int q = 0; q < 8; q++) fma2(accp, zp[q], wp[q]);
        float lo, hi; unpk(accp, lo, hi);
        float acc = bb + lo + hi;
        g_h1[(size_t)(base + r) * 128 + tid] = acc;
        float ch = cnt_sh[r] * acc;
        s += ch;
        ss = fmaf(ch, acc, ss);
    }
    atomicAdd(&g_sums1[tid], (double)s);
    atomicAdd(&g_sums1[128 + tid], (double)ss);
}

// ---------------------------------------------------------------------------
// FFMA2 SGEMM, column-pair packing.
// LAYER 0: 128 rows x 128 cols (h1->h2, W=w2), 16 col-groups.
// LAYER 1: 256 rows x  64 cols (h2->h3, W=w3),  8 col-groups.
// Thread (tx, ty): cols [tx*8, tx*8+8) as 4 pairs, rows [ty*8, ty*8+8).
// W smem: each 8-col group padded to 12 floats (48B stride -> conflict-free).
template <int LAYER>
__global__ void __launch_bounds__(256, 2) gemm_kernel(const float* __restrict__ W,
                                                      const float* __restrict__ bias,
                                                      const float* __restrict__ gam,
                                                      const float* __restrict__ bet,
                                                      double invB) {
    constexpr int NOUT = (LAYER == 0) ? 128 : 64;
    constexpr int ROWS = (LAYER == 0) ? 128 : 256;
    constexpr int NG   = NOUT / 8;         // col groups: 16 / 8
    constexpr int WROW = NG * 12;          // padded W row: 192 / 96 floats
    constexpr int TNX  = NG;               // threads along cols
    constexpr int TPR  = 256 / ROWS;       // staging threads per row: 2 / 1
    constexpr int QPT  = 4 / TPR;          // k-quads staged per thread: 2 / 4
    constexpr int NWQ  = NOUT / 64;        // W float4 loads per thread: 2 / 1

    const float*  in_tab   = (LAYER == 0) ? g_h1 : g_h2;
    float*        out_tab  = (LAYER == 0) ? g_h2 : g_h3;
    const double* sums_in  = (LAYER == 0) ? g_sums1 : g_sums2;
    double*       sums_out = (LAYER == 0) ? g_sums2 : g_sums3;

    __shared__ __align__(16) float zt[2][16][ROWS];
    __shared__ __align__(16) float wtp[2][16][WROW];
    __shared__ float a_sh[128], c_sh[128];
    __shared__ float cnt_sh[ROWS];
    __shared__ float psum[NOUT], psum2[NOUT];

    int tid   = threadIdx.x;
    int base  = blockIdx.x * ROWS;
    int nrows = min(ROWS, UNQ - base);

    if (tid < 128) {
        double mu  = sums_in[tid] * invB;
        double var = sums_in[128 + tid] * invB - mu * mu;
        float aj = __ldg(&gam[tid]) * rsqrtf((float)var + 1e-5f);
        a_sh[tid] = aj;
        c_sh[tid] = __ldg(&bet[tid]) - aj * (float)mu;
    }
    #pragma unroll
    for (int r = tid; r < ROWS; r += 256)
        cnt_sh[r] = (base + r < UNQ) ? (float)__ldg(&g_hist[base + r]) : 0.0f;
    if (tid < NOUT) { psum[tid] = 0.0f; psum2[tid] = 0.0f; }

    __syncthreads();   // a_sh/c_sh visible before any prefetch

    // staging roles
    const int zrow = tid % ROWS;
    const int zq0  = tid / ROWS;
    const bool zvalid = (zrow < nrows);
    const float* zsrc = in_tab + (size_t)(base + zrow) * 128;

    // compute roles
    const int tx = tid % TNX;
    const int ty = tid / TNX;

    float4 pz[QPT];
    float4 pw[NWQ];

    auto prefetch = [&](int c) {
        #pragma unroll
        for (int j = 0; j < QPT; j++) {
            int kg = c * 16 + (zq0 + j * TPR) * 4;
            float4 v = zvalid ? __ldg(reinterpret_cast<const float4*>(zsrc + kg))
                              : make_float4(0.f, 0.f, 0.f, 0.f);
            float4 av = *reinterpret_cast<const float4*>(&a_sh[kg]);
            float4 cv = *reinterpret_cast<const float4*>(&c_sh[kg]);
            v.x = fmaxf(fmaf(av.x, v.x, cv.x), 0.0f);
            v.y = fmaxf(fmaf(av.y, v.y, cv.y), 0.0f);
            v.z = fmaxf(fmaf(av.z, v.z, cv.z), 0.0f);
            v.w = fmaxf(fmaf(av.w, v.w, cv.w), 0.0f);
            if (!zvalid) v = make_float4(0.f, 0.f, 0.f, 0.f);
            pz[j] = v;
        }
        #pragma unroll
        for (int q = 0; q < NWQ; q++) {
            int f  = tid + q * 256;
            int k  = f / (NOUT / 4);
            int c4 = f % (NOUT / 4);
            pw[q] = __ldg(reinterpret_cast<const float4*>(W + (size_t)(c * 16 + k) * NOUT) + c4);
        }
    };

    auto store_stage = [&](int buf) {
        #pragma unroll
        for (int j = 0; j < QPT; j++) {
            int kk = (zq0 + j * TPR) * 4;
            zt[buf][kk + 0][zrow] = pz[j].x;
            zt[buf][kk + 1][zrow] = pz[j].y;
            zt[buf][kk + 2][zrow] = pz[j].z;
            zt[buf][kk + 3][zrow] = pz[j].w;
        }
        #pragma unroll
        for (int q = 0; q < NWQ; q++) {
            int f  = tid + q * 256;
            int k  = f / (NOUT / 4);
            int c4 = f % (NOUT / 4);
            // group g = c4>>1 padded to 12 floats; sub-half at (c4&1)*4
            *reinterpret_cast<float4*>(&wtp[buf][k][(c4 >> 1) * 12 + (c4 & 1) * 4]) = pw[q];
        }
    };

    unsigned long long acc[8][4];
    #pragma unroll
    for (int i = 0; i < 8; i++)
        #pragma unroll
        for (int jp = 0; jp < 4; jp++) acc[i][jp] = 0ull;

    prefetch(0);
    store_stage(0);
    __syncthreads();

    for (int c = 0; c < 8; c++) {
        int buf = c & 1;
        if (c < 7) prefetch(c + 1);

        #pragma unroll
        for (int k = 0; k < 16; k++) {
            // z rows ty*8..ty*8+7: broadcast LDS.128 x2, then dup to pairs
            float4 za = *reinterpret_cast<const float4*>(&zt[buf][k][ty * 8]);
            float4 zb = *reinterpret_cast<const float4*>(&zt[buf][k][ty * 8 + 4]);
            unsigned long long zd[8];
            zd[0] = dup2(za.x); zd[1] = dup2(za.y);
            zd[2] = dup2(za.z); zd[3] = dup2(za.w);
            zd[4] = dup2(zb.x); zd[5] = dup2(zb.y);
            zd[6] = dup2(zb.z); zd[7] = dup2(zb.w);

            // W col pairs: natural from two LDS.128 at 48B-strided group
            const ulonglong2* wb =
                reinterpret_cast<const ulonglong2*>(&wtp[buf][k][tx * 12]);
            ulonglong2 t0 = wb[0];   // (w0,w1), (w2,w3)
            ulonglong2 t1 = wb[1];   // (w4,w5), (w6,w7)
            unsigned long long wp[4] = {t0.x, t0.y, t1.x, t1.y};

            #pragma unroll
            for (int i = 0; i < 8; i++)
                #pragma unroll
                for (int jp = 0; jp < 4; jp++)
                    fma2(acc[i][jp], zd[i], wp[jp]);
        }

        if (c < 7) store_stage(buf ^ 1);
        __syncthreads();
    }

    // epilogue: bias, store, fused weighted stats
    float bv[8];
    {
        float4 b0 = __ldg(reinterpret_cast<const float4*>(bias) + tx * 2);
        float4 b1 = __ldg(reinterpret_cast<const float4*>(bias) + tx * 2 + 1);
        bv[0] = b0.x; bv[1] = b0.y; bv[2] = b0.z; bv[3] = b0.w;
        bv[4] = b1.x; bv[5] = b1.y; bv[6] = b1.z; bv[7] = b1.w;
    }

    float s[8], ssq[8];
    #pragma unroll
    for (int j = 0; j < 8; j++) { s[j] = 0.0f; ssq[j] = 0.0f; }

    #pragma unroll
    for (int i = 0; i < 8; i++) {
        int r = ty * 8 + i;
        float cnt = cnt_sh[r];
        float v[8];
        #pragma unroll
        for (int jp = 0; jp < 4; jp++) {
            float lo, hi; unpk(acc[i][jp], lo, hi);
            v[2 * jp]     = lo + bv[2 * jp];
            v[2 * jp + 1] = hi + bv[2 * jp + 1];
        }
        #pragma unroll
        for (int j = 0; j < 8; j++) {
            float cv = cnt * v[j];
            s[j] += cv;
            ssq[j] = fmaf(cv, v[j], ssq[j]);
        }
        if (r < nrows) {
            float* op = out_tab + (size_t)(base + r) * NOUT + tx * 8;
            reinterpret_cast<float4*>(op)[0] = make_float4(v[0], v[1], v[2], v[3]);
            reinterpret_cast<float4*>(op)[1] = make_float4(v[4], v[5], v[6], v[7]);
        }
    }

    #pragma unroll
    for (int j = 0; j < 8; j++) {
        atomicAdd(&psum[tx * 8 + j], s[j]);
        atomicAdd(&psum2[tx * 8 + j], ssq[j]);
    }
    __syncthreads();
    if (tid < NOUT) {
        atomicAdd(&sums_out[tid], (double)psum[tid]);
        atomicAdd(&sums_out[NOUT + tid], (double)psum2[tid]);
    }
}

// ---------------------------------------------------------------------------
__global__ void __launch_bounds__(256) l4_kernel(const float* __restrict__ w4,
                                                 const float* __restrict__ b4,
                                                 const float* __restrict__ g3,
                                                 const float* __restrict__ be3,
                                                 double invB) {
    __shared__ float a_sh[64], c_sh[64];
    int tid = threadIdx.x;
    if (tid < 64) {
        double mu  = g_sums3[tid] * invB;
        double var = g_sums3[64 + tid] * invB - mu * mu;
        float aj = __ldg(&g3[tid]) * rsqrtf((float)var + 1e-5f);
        a_sh[tid] = aj;
        c_sh[tid] = __ldg(&be3[tid]) - aj * (float)mu;
    }
    __syncthreads();

    int u = blockIdx.x * blockDim.x + tid;
    if (u >= UNQ) return;
    const float4* hr = reinterpret_cast<const float4*>(g_h3 + (size_t)u * 64);
    float acc = __ldg(b4);
    #pragma unroll
    for (int q = 0; q < 16; q++) {
        float4 h = hr[q];
        int k = q * 4;
        float z0 = fmaxf(fmaf(a_sh[k + 0], h.x, c_sh[k + 0]), 0.0f);
        float z1 = fmaxf(fmaf(a_sh[k + 1], h.y, c_sh[k + 1]), 0.0f);
        float z2 = fmaxf(fmaf(a_sh[k + 2], h.z, c_sh[k + 2]), 0.0f);
        float z3 = fmaxf(fmaf(a_sh[k + 3], h.w, c_sh[k + 3]), 0.0f);
        acc = fmaf(z0, __ldg(&w4[k + 0]), acc);
        acc = fmaf(z1, __ldg(&w4[k + 1]), acc);
        acc = fmaf(z2, __ldg(&w4[k + 2]), acc);
        acc = fmaf(z3, __ldg(&w4[k + 3]), acc);
    }
    g_out_tab[u] = 1.0f / (1.0f + expf(-acc));
}

// ---------------------------------------------------------------------------
__global__ void gather_kernel(float* __restrict__ out, int B) {
    int i = blockIdx.x * blockDim.x + threadIdx.x;
    if (i >= B) return;
    out[i] = g_out_tab[g_idx[i]];
}

// ============================================================================
extern "C" void kernel_launch(void* const* d_in, const int* in_sizes, int n_in,
                              void* d_out, int out_size) {
    const float* x   = (const float*)d_in[0];
    const float* w1  = (const float*)d_in[1];
    const float* b1  = (const float*)d_in[2];
    const float* g1  = (const float*)d_in[3];
    const float* be1 = (const float*)d_in[4];
    const float* w2  = (const float*)d_in[5];
    const float* b2  = (const float*)d_in[6];
    const float* g2  = (const float*)d_in[7];
    const float* be2 = (const float*)d_in[8];
    const float* w3  = (const float*)d_in[9];
    const float* b3  = (const float*)d_in[10];
    const float* g3  = (const float*)d_in[11];
    const float* be3 = (const float*)d_in[12];
    const float* w4  = (const float*)d_in[13];
    const float* b4  = (const float*)d_in[14];
    float* out = (float*)d_out;

    int B = in_sizes[0] / 16;
    double invB = 1.0 / (double)B;

    zero_kernel<<<64, 256>>>();
    hist_kernel<<<(B + 255) / 256, 256>>>(x, B);
    l1_kernel<<<(UNQ + 127) / 128, 128>>>(w1, b1);
    gemm_kernel<0><<<(UNQ + 127) / 128, 256>>>(w2, b2, g1, be1, invB);
    gemm_kernel<1><<<(UNQ + 255) / 256, 256>>>(w3, b3, g2, be2, invB);
    l4_kernel<<<(UNQ + 255) / 256, 256>>>(w4, b4, g3, be3, invB);
    gather_kernel<<<(B + 255) / 256, 256>>>(out, B);
}